// round 17
// baseline (speedup 1.0000x reference)
#include <cuda_runtime.h>
#include <cuda_bf16.h>

// Problem constants (fixed by the reference: B=2048, C=16, H=32, W=32 -> F=16384)
#define B_SAMPLES 2048
#define F_FEATS   16384
#define THREADS   256

// Scratch (no device allocation allowed).
__device__ float        g_per_sample[B_SAMPLES];
__device__ unsigned int g_arrive_count = 0;   // reset by the last block each run

// sm_10x 256-bit global loads (LDG.E.256): double the bytes per outstanding
// load -> higher bytes-in-flight at the same scoreboard depth.
__device__ __forceinline__ void ldcg_v8(const float* __restrict__ p, float* v) {
    asm volatile("ld.global.cg.v8.f32 {%0,%1,%2,%3,%4,%5,%6,%7}, [%8];"
                 : "=f"(v[0]), "=f"(v[1]), "=f"(v[2]), "=f"(v[3]),
                   "=f"(v[4]), "=f"(v[5]), "=f"(v[6]), "=f"(v[7])
                 : "l"(p));
}
__device__ __forceinline__ void ldca_v8(const float* __restrict__ p, float* v) {
    asm volatile("ld.global.ca.v8.f32 {%0,%1,%2,%3,%4,%5,%6,%7}, [%8];"
                 : "=f"(v[0]), "=f"(v[1]), "=f"(v[2]), "=f"(v[3]),
                   "=f"(v[4]), "=f"(v[5]), "=f"(v[6]), "=f"(v[7])
                 : "l"(p));
}

__global__ __launch_bounds__(THREADS, 6)   // allow ~40-42 regs; 48 warps/SM
void fnmse_fused_kernel(const float* __restrict__ out,
                        const float* __restrict__ tgt,
                        const float* __restrict__ fw,
                        float* __restrict__ d_out)
{
    const int b   = blockIdx.x;
    const int tid = threadIdx.x;

    const float* o_row = out + (size_t)b * F_FEATS;
    const float* t_row = tgt + (size_t)b * F_FEATS;

    float ssq = 0.0f;
    float cnt = 0.0f;

    // One row per CTA, 256 threads, 256-bit loads: 8 floats/thread/iter ->
    // 8 fully unrolled iterations (deep unroll preserved; request width 2x).
#pragma unroll
    for (int it = 0; it < F_FEATS / (THREADS * 8); ++it) {
        const size_t off = (size_t)(it * THREADS + tid) * 8;
        float o[8], t[8], w[8];
        ldcg_v8(o_row + off, o);
        ldcg_v8(t_row + off, t);
        ldca_v8(fw + off, w);

#pragma unroll
        for (int k = 0; k < 8; ++k) {
            bool  m = (t[k] == t[k]);          // !isnan
            float r = m ? (t[k] - o[k]) : 0.0f;
            float s = r * w[k];
            ssq = fmaf(s, s, ssq);
            cnt += m ? 1.0f : 0.0f;
        }
    }

    // Warp reduction
#pragma unroll
    for (int off = 16; off > 0; off >>= 1) {
        ssq += __shfl_down_sync(0xFFFFFFFFu, ssq, off);
        cnt += __shfl_down_sync(0xFFFFFFFFu, cnt, off);
    }

    __shared__ float s_ssq[THREADS / 32];
    __shared__ float s_cnt[THREADS / 32];
    const int lane = tid & 31;
    const int wid  = tid >> 5;
    if (lane == 0) { s_ssq[wid] = ssq; s_cnt[wid] = cnt; }
    __syncthreads();

    // Warps 1..7 retire immediately — no fence, no trailing barrier.
    if (wid != 0) return;

    float vs = (lane < THREADS / 32) ? s_ssq[lane] : 0.0f;
    float vc = (lane < THREADS / 32) ? s_cnt[lane] : 0.0f;
#pragma unroll
    for (int off = 4; off > 0; off >>= 1) {
        vs += __shfl_down_sync(0xFFFFFFFFu, vs, off);
        vc += __shfl_down_sync(0xFFFFFFFFu, vc, off);
    }

    int is_last = 0;
    if (lane == 0) {
        // Deposit the per-sample value, then release-arrive (the release orders
        // the STG; acq_rel gives the last block acquire for the readback).
        g_per_sample[b] = vs / vc;
        unsigned int prev;
        asm volatile("atom.add.acq_rel.gpu.global.u32 %0, [%1], 1;"
                     : "=r"(prev) : "l"(&g_arrive_count) : "memory");
        is_last = (prev == (unsigned int)(gridDim.x - 1));
    }
    is_last = __shfl_sync(0xFFFFFFFFu, is_last, 0);

    // Last-arriving block: warp 0 alone, fixed-order deterministic combine
    // (8KB, L2-resident, 16 float4 loads per lane).
    if (is_last) {
        const float4* p4 = reinterpret_cast<const float4*>(g_per_sample);
        float s = 0.0f;
#pragma unroll
        for (int r = 0; r < B_SAMPLES / 4 / 32; ++r) {
            float4 a = p4[r * 32 + lane];
            s += (a.x + a.y) + (a.z + a.w);
        }
#pragma unroll
        for (int off = 16; off > 0; off >>= 1)
            s += __shfl_down_sync(0xFFFFFFFFu, s, off);
        if (lane == 0) {
            d_out[0] = s;
            g_arrive_count = 0u;   // reset for next graph replay
        }
    }
}

extern "C" void kernel_launch(void* const* d_in, const int* in_sizes, int n_in,
                              void* d_out, int out_size)
{
    // metadata order: output, target, e_exp, sample_weight, feature_weight
    const float* out = (const float*)d_in[0];
    const float* tgt = (const float*)d_in[1];
    // d_in[2] (e_exp) and d_in[3] (sample_weight) are unused by the reference.
    const float* fw  = (const float*)d_in[4];

    fnmse_fused_kernel<<<B_SAMPLES, THREADS>>>(out, tgt, fw, (float*)d_out);
}